// round 3
// baseline (speedup 1.0000x reference)
#include <cuda_runtime.h>
#include <math.h>
#include <cstdint>

#define NN 100000
#define EE 600000
#define DD 128
#define ETOT (EE + NN)

// ---------------- scratch (static device globals; no allocation) ----------------
__device__ float g_x0[NN * DD];
__device__ float g_x1[NN * DD];
__device__ float g_h [NN * DD];
__device__ float g_el[NN * 4];
__device__ float g_er[NN * 4];
__device__ int   g_rowptr[NN + 1];
__device__ int   g_cnt[NN];
__device__ int   g_csr[ETOT];

// ---------------- CSR build ------------------------------------------------------
__global__ void k_cnt_init() {
    int i = blockIdx.x * blockDim.x + threadIdx.x;
    if (i < NN) g_cnt[i] = 1;
}
__global__ void k_hist(const int* __restrict__ dst) {
    int i = blockIdx.x * blockDim.x + threadIdx.x;
    if (i < EE) atomicAdd(&g_cnt[dst[i]], 1);
}
__global__ void k_scan() {
    __shared__ int ss[1024];
    int t = threadIdx.x;
    const int chunk = (NN + 1023) / 1024;
    int beg = t * chunk, end = min(beg + chunk, NN);
    int s = 0;
    for (int i = beg; i < end; i++) s += g_cnt[i];
    ss[t] = s;
    __syncthreads();
    for (int o = 1; o < 1024; o <<= 1) {
        int v = (t >= o) ? ss[t - o] : 0;
        __syncthreads();
        ss[t] += v;
        __syncthreads();
    }
    int run = (t == 0) ? 0 : ss[t - 1];
    for (int i = beg; i < end; i++) {
        int c = g_cnt[i];
        g_rowptr[i] = run;
        g_cnt[i] = run;
        run += c;
    }
    if (t == 1023) g_rowptr[NN] = ss[1023];
}
__global__ void k_scatter(const int* __restrict__ src, const int* __restrict__ dst) {
    int i = blockIdx.x * blockDim.x + threadIdx.x;
    if (i < EE) {
        int p = atomicAdd(&g_cnt[dst[i]], 1);
        g_csr[p] = src[i];
    } else if (i < EE + NN) {
        int n = i - EE;
        int p = atomicAdd(&g_cnt[n], 1);
        g_csr[p] = n;
    }
}

// ---------------- x init ---------------------------------------------------------
__global__ void k_init_x(const float* __restrict__ w, const float* __restrict__ linW,
                         const float* __restrict__ linb) {
    int i = blockIdx.x * blockDim.x + threadIdx.x;
    if (i < NN * DD) {
        int n = i >> 7, d = i & 127;
        g_x0[i] = w[n] * linW[d] + linb[d];
    }
}

// ---------------- mma.sync tf32 helpers -----------------------------------------
__device__ __forceinline__ uint32_t tf32_of(float f) {
    uint32_t u;
    asm("cvt.rna.tf32.f32 %0, %1;" : "=r"(u) : "f"(f));
    return u;
}
__device__ __forceinline__ void mma8(float* d, const uint32_t* a, const uint32_t* b) {
    asm volatile(
        "mma.sync.aligned.m16n8k8.row.col.f32.tf32.tf32.f32 "
        "{%0,%1,%2,%3}, {%4,%5,%6,%7}, {%8,%9}, {%0,%1,%2,%3};"
        : "+f"(d[0]), "+f"(d[1]), "+f"(d[2]), "+f"(d[3])
        : "r"(a[0]), "r"(a[1]), "r"(a[2]), "r"(a[3]), "r"(b[0]), "r"(b[1]));
}

// ---------------- GEMM h = act(x) @ W^T, fused el/er (3xTF32 mma.sync) ----------
// 128 rows x 128 cols per CTA, 8 warps: warp = (rg = warp&3 -> 32 rows) x
// (ch = warp>>2 -> 64 cols). 3xTF32: acc += ahi*bhi + alo*bhi + ahi*blo.
#define XS_LD 132

template <bool ACT, int INBUF>
__global__ void __launch_bounds__(256) k_gemm_mma(const float* __restrict__ Wm,
                                                  const float* __restrict__ al,
                                                  const float* __restrict__ ar) {
    extern __shared__ float sm[];
    float* Xs   = sm;                    // [128][132] fp32
    float* Whi  = sm + 128 * XS_LD;      // [128][132] tf32-in-f32
    float* Wlo  = Whi + 128 * XS_LD;     // [128][132]
    float* attn = Wlo + 128 * XS_LD;     // [256]
    const float* __restrict__ x = INBUF ? g_x1 : g_x0;
    int tid = threadIdx.x, lane = tid & 31, warp = tid >> 5;
    int row0 = blockIdx.x * 128;

    attn[tid] = (tid < 128) ? al[tid] : ar[tid - 128];

    // X tile (fp32, leaky on load); zero-pad OOB rows
    for (int i = tid; i < 128 * 32; i += 256) {
        int r = i >> 5, c4 = i & 31;
        float4 v = make_float4(0.f, 0.f, 0.f, 0.f);
        if (row0 + r < NN) {
            v = *(const float4*)&x[(row0 + r) * 128 + c4 * 4];
            if (ACT) {
                v.x = v.x >= 0.f ? v.x : 0.01f * v.x;
                v.y = v.y >= 0.f ? v.y : 0.01f * v.y;
                v.z = v.z >= 0.f ? v.z : 0.01f * v.z;
                v.w = v.w >= 0.f ? v.w : 0.01f * v.w;
            }
        }
        *(float4*)&Xs[r * XS_LD + c4 * 4] = v;
    }
    // W tile, split hi/lo
    for (int i = tid; i < 128 * 32; i += 256) {
        int n = i >> 5, c4 = i & 31;
        float4 v = *(const float4*)&Wm[n * 128 + c4 * 4];
        float hx = __uint_as_float(tf32_of(v.x));
        float hy = __uint_as_float(tf32_of(v.y));
        float hz = __uint_as_float(tf32_of(v.z));
        float hw = __uint_as_float(tf32_of(v.w));
        *(float4*)&Whi[n * XS_LD + c4 * 4] = make_float4(hx, hy, hz, hw);
        *(float4*)&Wlo[n * XS_LD + c4 * 4] =
            make_float4(__uint_as_float(tf32_of(v.x - hx)), __uint_as_float(tf32_of(v.y - hy)),
                        __uint_as_float(tf32_of(v.z - hz)), __uint_as_float(tf32_of(v.w - hw)));
    }
    __syncthreads();

    int rg = warp & 3, ch = warp >> 2;
    int gid = lane >> 2, tig = lane & 3;
    float acc[2][8][4];
#pragma unroll
    for (int m = 0; m < 2; m++)
#pragma unroll
        for (int t = 0; t < 8; t++)
#pragma unroll
            for (int j = 0; j < 4; j++) acc[m][t][j] = 0.f;

    for (int ks = 0; ks < 16; ks++) {
        int k0 = ks * 8;
        uint32_t ahi[2][4], alo[2][4];
#pragma unroll
        for (int m = 0; m < 2; m++) {
            int rb = rg * 32 + m * 16;
            float f0 = Xs[(rb + gid) * XS_LD + k0 + tig];
            float f1 = Xs[(rb + gid + 8) * XS_LD + k0 + tig];
            float f2 = Xs[(rb + gid) * XS_LD + k0 + tig + 4];
            float f3 = Xs[(rb + gid + 8) * XS_LD + k0 + tig + 4];
            ahi[m][0] = tf32_of(f0); alo[m][0] = tf32_of(f0 - __uint_as_float(ahi[m][0]));
            ahi[m][1] = tf32_of(f1); alo[m][1] = tf32_of(f1 - __uint_as_float(ahi[m][1]));
            ahi[m][2] = tf32_of(f2); alo[m][2] = tf32_of(f2 - __uint_as_float(ahi[m][2]));
            ahi[m][3] = tf32_of(f3); alo[m][3] = tf32_of(f3 - __uint_as_float(ahi[m][3]));
        }
#pragma unroll
        for (int t = 0; t < 8; t++) {
            int n = ch * 64 + t * 8 + gid;
            uint32_t bhi[2], blo[2];
            bhi[0] = __float_as_uint(Whi[n * XS_LD + k0 + tig]);
            bhi[1] = __float_as_uint(Whi[n * XS_LD + k0 + tig + 4]);
            blo[0] = __float_as_uint(Wlo[n * XS_LD + k0 + tig]);
            blo[1] = __float_as_uint(Wlo[n * XS_LD + k0 + tig + 4]);
#pragma unroll
            for (int m = 0; m < 2; m++) {
                mma8(acc[m][t], ahi[m], bhi);
                mma8(acc[m][t], alo[m], bhi);
                mma8(acc[m][t], ahi[m], blo);
            }
        }
    }

    // epilogue: h store (float2 per tile-row) + el/er partial dots + quad reduce
#pragma unroll
    for (int m = 0; m < 2; m++) {
        int r = row0 + rg * 32 + m * 16 + gid;  // row for acc[.][.][0..1]; r+8 for [2..3]
        float el0 = 0.f, el1 = 0.f, er0 = 0.f, er1 = 0.f;   // row r, heads (ch*2, ch*2+1)
        float fl0 = 0.f, fl1 = 0.f, fr0 = 0.f, fr1 = 0.f;   // row r+8
#pragma unroll
        for (int t = 0; t < 8; t++) {
            int c0 = ch * 64 + t * 8 + tig * 2;
            float w0l = attn[c0], w1l = attn[c0 + 1];
            float w0r = attn[128 + c0], w1r = attn[128 + c0 + 1];
            float d0 = acc[m][t][0], d1 = acc[m][t][1];
            float d2 = acc[m][t][2], d3 = acc[m][t][3];
            if (t < 4) {
                el0 = fmaf(d0, w0l, fmaf(d1, w1l, el0));
                er0 = fmaf(d0, w0r, fmaf(d1, w1r, er0));
                fl0 = fmaf(d2, w0l, fmaf(d3, w1l, fl0));
                fr0 = fmaf(d2, w0r, fmaf(d3, w1r, fr0));
            } else {
                el1 = fmaf(d0, w0l, fmaf(d1, w1l, el1));
                er1 = fmaf(d0, w0r, fmaf(d1, w1r, er1));
                fl1 = fmaf(d2, w0l, fmaf(d3, w1l, fl1));
                fr1 = fmaf(d2, w0r, fmaf(d3, w1r, fr1));
            }
            if (r < NN)     *(float2*)&g_h[r * 128 + c0]       = make_float2(d0, d1);
            if (r + 8 < NN) *(float2*)&g_h[(r + 8) * 128 + c0] = make_float2(d2, d3);
        }
#pragma unroll
        for (int o = 1; o <= 2; o <<= 1) {
            el0 += __shfl_xor_sync(0xffffffffu, el0, o);
            el1 += __shfl_xor_sync(0xffffffffu, el1, o);
            er0 += __shfl_xor_sync(0xffffffffu, er0, o);
            er1 += __shfl_xor_sync(0xffffffffu, er1, o);
            fl0 += __shfl_xor_sync(0xffffffffu, fl0, o);
            fl1 += __shfl_xor_sync(0xffffffffu, fl1, o);
            fr0 += __shfl_xor_sync(0xffffffffu, fr0, o);
            fr1 += __shfl_xor_sync(0xffffffffu, fr1, o);
        }
        if (tig == 0) {
            int hb = ch * 2;
            if (r < NN) {
                g_el[r * 4 + hb] = el0;  g_el[r * 4 + hb + 1] = el1;
                g_er[r * 4 + hb] = er0;  g_er[r * 4 + hb + 1] = er1;
            }
            if (r + 8 < NN) {
                g_el[(r + 8) * 4 + hb] = fl0;  g_el[(r + 8) * 4 + hb + 1] = fl1;
                g_er[(r + 8) * 4 + hb] = fr0;  g_er[(r + 8) * 4 + hb + 1] = fr1;
            }
        }
    }
}

#define SM_GEMM ((3 * 128 * XS_LD + 256) * 4)

// ---------------- edge softmax + aggregation: one warp per dst node -------------
__device__ __forceinline__ float sel4(float4 v, int hh) {
    return (hh & 2) ? ((hh & 1) ? v.w : v.z) : ((hh & 1) ? v.y : v.x);
}

template <int OUTBUF>
__global__ void __launch_bounds__(256) k_agg(const float* __restrict__ bias) {
    float* __restrict__ xout = OUTBUF ? g_x1 : g_x0;
    int gw = (blockIdx.x * blockDim.x + threadIdx.x) >> 5;
    int lane = threadIdx.x & 31;
    if (gw >= NN) return;
    int n = gw;
    int beg = g_rowptr[n], end = g_rowptr[n + 1];
    float4 er4 = *(const float4*)&g_er[n * 4];

    float m0 = -3.4e38f, m1 = m0, m2 = m0, m3 = m0;
    for (int j = beg + lane; j < end; j += 32) {
        int s = g_csr[j];
        float4 el4 = *(const float4*)&g_el[s * 4];
        float e0 = el4.x + er4.x; e0 = e0 >= 0.f ? e0 : 0.2f * e0;
        float e1 = el4.y + er4.y; e1 = e1 >= 0.f ? e1 : 0.2f * e1;
        float e2 = el4.z + er4.z; e2 = e2 >= 0.f ? e2 : 0.2f * e2;
        float e3 = el4.w + er4.w; e3 = e3 >= 0.f ? e3 : 0.2f * e3;
        m0 = fmaxf(m0, e0); m1 = fmaxf(m1, e1);
        m2 = fmaxf(m2, e2); m3 = fmaxf(m3, e3);
    }
#pragma unroll
    for (int o = 16; o > 0; o >>= 1) {
        m0 = fmaxf(m0, __shfl_xor_sync(0xffffffffu, m0, o));
        m1 = fmaxf(m1, __shfl_xor_sync(0xffffffffu, m1, o));
        m2 = fmaxf(m2, __shfl_xor_sync(0xffffffffu, m2, o));
        m3 = fmaxf(m3, __shfl_xor_sync(0xffffffffu, m3, o));
    }

    int hh = lane >> 3;
    float mh = (hh & 2) ? ((hh & 1) ? m3 : m2) : ((hh & 1) ? m1 : m0);
    float erh = sel4(er4, hh);

    float a0 = 0.f, a1 = 0.f, a2 = 0.f, a3 = 0.f, sacc = 0.f;
    for (int j = beg; j < end; j++) {
        int s = g_csr[j];
        float4 el4 = *(const float4*)&g_el[s * 4];
        float e = sel4(el4, hh) + erh;
        e = e >= 0.f ? e : 0.2f * e;
        float p = __expf(e - mh);
        float4 hv = *(const float4*)&g_h[s * 128 + lane * 4];
        a0 = fmaf(p, hv.x, a0); a1 = fmaf(p, hv.y, a1);
        a2 = fmaf(p, hv.z, a2); a3 = fmaf(p, hv.w, a3);
        sacc += p;
    }
    float inv = 1.f / sacc;
    int col = lane * 4;
    float4 bv = *(const float4*)&bias[col];
    *(float4*)&xout[n * 128 + col] =
        make_float4(fmaf(a0, inv, bv.x), fmaf(a1, inv, bv.y),
                    fmaf(a2, inv, bv.z), fmaf(a3, inv, bv.w));
}

// ---------------- prediction head ----------------------------------------------
__global__ void __launch_bounds__(256) k_pred(const float* __restrict__ pW,
                                              const float* __restrict__ pb,
                                              float* __restrict__ out) {
    int gw = (blockIdx.x * blockDim.x + threadIdx.x) >> 5;
    int lane = threadIdx.x & 31;
    if (gw >= NN) return;
    float4 xv = *(const float4*)&g_x1[gw * 128 + lane * 4];
    float4 wv = *(const float4*)&pW[lane * 4];
    float s = xv.x * wv.x + xv.y * wv.y + xv.z * wv.z + xv.w * wv.w;
#pragma unroll
    for (int o = 16; o > 0; o >>= 1) s += __shfl_xor_sync(0xffffffffu, s, o);
    if (lane == 0) out[gw] = s + pb[0];
}

// ---------------- launch --------------------------------------------------------
extern "C" void kernel_launch(void* const* d_in, const int* in_sizes, int n_in,
                              void* d_out, int out_size) {
    const float* weights = (const float*)d_in[0];
    const float* linW    = (const float*)d_in[1];
    const float* linb    = (const float*)d_in[2];
    const float* fcW     = (const float*)d_in[3];
    const float* al      = (const float*)d_in[4];
    const float* ar      = (const float*)d_in[5];
    const float* cb      = (const float*)d_in[6];
    const float* pW      = (const float*)d_in[7];
    const float* pb      = (const float*)d_in[8];
    const int*   src     = (const int*)d_in[9];
    const int*   dst     = (const int*)d_in[10];
    float* out = (float*)d_out;

    static bool attr_done = false;
    if (!attr_done) {
        cudaFuncSetAttribute(k_gemm_mma<false, 0>, cudaFuncAttributeMaxDynamicSharedMemorySize, SM_GEMM);
        cudaFuncSetAttribute(k_gemm_mma<true, 1>,  cudaFuncAttributeMaxDynamicSharedMemorySize, SM_GEMM);
        cudaFuncSetAttribute(k_gemm_mma<true, 0>,  cudaFuncAttributeMaxDynamicSharedMemorySize, SM_GEMM);
        attr_done = true;
    }

    k_cnt_init<<<(NN + 255) / 256, 256>>>();
    k_hist<<<(EE + 255) / 256, 256>>>(dst);
    k_scan<<<1, 1024>>>();
    k_scatter<<<(EE + NN + 255) / 256, 256>>>(src, dst);

    k_init_x<<<(NN * DD + 255) / 256, 256>>>(weights, linW, linb);

    const int GB = (NN + 127) / 128;
    const int AB = (NN * 32 + 255) / 256;

    k_gemm_mma<false, 0><<<GB, 256, SM_GEMM>>>(fcW, al, ar);
    k_agg<1><<<AB, 256>>>(cb);
    k_gemm_mma<true, 1><<<GB, 256, SM_GEMM>>>(fcW + DD * DD, al + DD, ar + DD);
    k_agg<0><<<AB, 256>>>(cb + DD);
    k_gemm_mma<true, 0><<<GB, 256, SM_GEMM>>>(fcW + 2 * DD * DD, al + 2 * DD, ar + 2 * DD);
    k_agg<1><<<AB, 256>>>(cb + 2 * DD);

    k_pred<<<AB, 256>>>(pW, pb, out);
}

// round 4
// speedup vs baseline: 1.3392x; 1.3392x over previous
#include <cuda_runtime.h>
#include <math.h>
#include <cstdint>

#define NN 100000
#define EE 600000
#define DD 128
#define ETOT (EE + NN)

// ---------------- scratch (static device globals; no allocation) ----------------
__device__ float  g_x0[NN * DD];
__device__ float  g_h [NN * DD];
__device__ float  g_el[NN * 4];
__device__ float  g_er[NN * 4];
__device__ float4 g_T [NN];          // per-node per-head A_h = sum(alpha*w_src)
__device__ float  g_u [DD];          // W0 @ linW
__device__ float  g_vb[DD];          // W0 @ linb + conv_b[0]
__device__ float  g_sc[16];          // CL[4], DL[4], CR[4], DR[4]
__device__ int    g_rowptr[NN + 1];
__device__ int    g_cnt[NN];
__device__ int    g_csr[ETOT];

// ---------------- CSR build ------------------------------------------------------
__global__ void k_cnt_init() {
    int i = blockIdx.x * blockDim.x + threadIdx.x;
    if (i < NN) g_cnt[i] = 1;
}
__global__ void k_hist(const int* __restrict__ dst) {
    int i = blockIdx.x * blockDim.x + threadIdx.x;
    if (i < EE) atomicAdd(&g_cnt[dst[i]], 1);
}
__global__ void k_scan() {
    __shared__ int ss[1024];
    int t = threadIdx.x;
    const int chunk = (NN + 1023) / 1024;
    int beg = t * chunk, end = min(beg + chunk, NN);
    int s = 0;
    for (int i = beg; i < end; i++) s += g_cnt[i];
    ss[t] = s;
    __syncthreads();
    for (int o = 1; o < 1024; o <<= 1) {
        int v = (t >= o) ? ss[t - o] : 0;
        __syncthreads();
        ss[t] += v;
        __syncthreads();
    }
    int run = (t == 0) ? 0 : ss[t - 1];
    for (int i = beg; i < end; i++) {
        int c = g_cnt[i];
        g_rowptr[i] = run;
        g_cnt[i] = run;
        run += c;
    }
    if (t == 1023) g_rowptr[NN] = ss[1023];
}
__global__ void k_scatter(const int* __restrict__ src, const int* __restrict__ dst) {
    int i = blockIdx.x * blockDim.x + threadIdx.x;
    if (i < EE) {
        int p = atomicAdd(&g_cnt[dst[i]], 1);
        g_csr[p] = src[i];
    } else if (i < EE + NN) {
        int n = i - EE;
        int p = atomicAdd(&g_cnt[n], 1);
        g_csr[p] = n;
    }
}

// ---------------- layer-0 analytic prep ------------------------------------------
// u = W0 @ linW, v = W0 @ linb ; vb = v + conv_b[0]
// CL[h] = <u_h, al0_h>, DL[h] = <v_h, al0_h>, CR[h] = <u_h, ar0_h>, DR[h] = <v_h, ar0_h>
__global__ void k_prep(const float* __restrict__ fcW, const float* __restrict__ linW,
                       const float* __restrict__ linb, const float* __restrict__ al,
                       const float* __restrict__ ar, const float* __restrict__ cb) {
    __shared__ float su[128], sv[128];
    int d = threadIdx.x;
    float uu = 0.f, vv = 0.f;
    for (int k = 0; k < 128; k++) {
        float w = fcW[d * 128 + k];
        uu = fmaf(w, linW[k], uu);
        vv = fmaf(w, linb[k], vv);
    }
    su[d] = uu;
    sv[d] = vv;
    g_u[d] = uu;
    g_vb[d] = vv + cb[d];
    __syncthreads();
    if (d < 16) {
        int type = d >> 2, h = d & 3;                 // 0:CL 1:DL 2:CR 3:DR
        const float* a = (type < 2) ? al : ar;
        const float* base = (type & 1) ? sv : su;
        float s = 0.f;
        for (int f = 0; f < 32; f++) s = fmaf(base[h * 32 + f], a[h * 32 + f], s);
        g_sc[type * 4 + h] = s;
    }
}

// ---------------- layer-0 aggregation: scalar sums only --------------------------
// e_h(edge) = leaky(w_src*CL_h + DL_h + w_dst*CR_h + DR_h)
// out0[n,c] = A_h*u[c] + vb[c], A_h = sum(p*w_src)/sum(p)
__global__ void __launch_bounds__(256) k_agg0(const float* __restrict__ w) {
    int gw = (blockIdx.x * blockDim.x + threadIdx.x) >> 5;
    int lane = threadIdx.x & 31;
    if (gw >= NN) return;
    int n = gw;
    int beg = g_rowptr[n], end = g_rowptr[n + 1];

    float CL0 = g_sc[0], CL1 = g_sc[1], CL2 = g_sc[2], CL3 = g_sc[3];
    float DL0 = g_sc[4], DL1 = g_sc[5], DL2 = g_sc[6], DL3 = g_sc[7];
    float wn = w[n];
    float er0 = fmaf(wn, g_sc[8],  g_sc[12]) ;
    float er1 = fmaf(wn, g_sc[9],  g_sc[13]) ;
    float er2 = fmaf(wn, g_sc[10], g_sc[14]) ;
    float er3 = fmaf(wn, g_sc[11], g_sc[15]) ;

    float m0 = -3.4e38f, m1 = m0, m2 = m0, m3 = m0;
    for (int j = beg + lane; j < end; j += 32) {
        float ws = w[g_csr[j]];
        float e0 = fmaf(ws, CL0, DL0) + er0; e0 = e0 >= 0.f ? e0 : 0.2f * e0;
        float e1 = fmaf(ws, CL1, DL1) + er1; e1 = e1 >= 0.f ? e1 : 0.2f * e1;
        float e2 = fmaf(ws, CL2, DL2) + er2; e2 = e2 >= 0.f ? e2 : 0.2f * e2;
        float e3 = fmaf(ws, CL3, DL3) + er3; e3 = e3 >= 0.f ? e3 : 0.2f * e3;
        m0 = fmaxf(m0, e0); m1 = fmaxf(m1, e1);
        m2 = fmaxf(m2, e2); m3 = fmaxf(m3, e3);
    }
#pragma unroll
    for (int o = 16; o > 0; o >>= 1) {
        m0 = fmaxf(m0, __shfl_xor_sync(0xffffffffu, m0, o));
        m1 = fmaxf(m1, __shfl_xor_sync(0xffffffffu, m1, o));
        m2 = fmaxf(m2, __shfl_xor_sync(0xffffffffu, m2, o));
        m3 = fmaxf(m3, __shfl_xor_sync(0xffffffffu, m3, o));
    }

    float S0 = 0.f, S1 = 0.f, S2 = 0.f, S3 = 0.f;
    float T0 = 0.f, T1 = 0.f, T2 = 0.f, T3 = 0.f;
    for (int j = beg + lane; j < end; j += 32) {
        float ws = w[g_csr[j]];
        float e0 = fmaf(ws, CL0, DL0) + er0; e0 = e0 >= 0.f ? e0 : 0.2f * e0;
        float e1 = fmaf(ws, CL1, DL1) + er1; e1 = e1 >= 0.f ? e1 : 0.2f * e1;
        float e2 = fmaf(ws, CL2, DL2) + er2; e2 = e2 >= 0.f ? e2 : 0.2f * e2;
        float e3 = fmaf(ws, CL3, DL3) + er3; e3 = e3 >= 0.f ? e3 : 0.2f * e3;
        float p0 = __expf(e0 - m0), p1 = __expf(e1 - m1);
        float p2 = __expf(e2 - m2), p3 = __expf(e3 - m3);
        S0 += p0; S1 += p1; S2 += p2; S3 += p3;
        T0 = fmaf(p0, ws, T0); T1 = fmaf(p1, ws, T1);
        T2 = fmaf(p2, ws, T2); T3 = fmaf(p3, ws, T3);
    }
#pragma unroll
    for (int o = 16; o > 0; o >>= 1) {
        S0 += __shfl_xor_sync(0xffffffffu, S0, o);
        S1 += __shfl_xor_sync(0xffffffffu, S1, o);
        S2 += __shfl_xor_sync(0xffffffffu, S2, o);
        S3 += __shfl_xor_sync(0xffffffffu, S3, o);
        T0 += __shfl_xor_sync(0xffffffffu, T0, o);
        T1 += __shfl_xor_sync(0xffffffffu, T1, o);
        T2 += __shfl_xor_sync(0xffffffffu, T2, o);
        T3 += __shfl_xor_sync(0xffffffffu, T3, o);
    }
    if (lane == 0)
        g_T[n] = make_float4(T0 / S0, T1 / S1, T2 / S2, T3 / S3);
}

// ---------------- GEMM h = leaky(x) @ W^T fused with el/er -----------------------
// MODE 0: x reconstructed from g_T (layer 1).  MODE 1: x from g_x0 (layer 2).
template <int MODE>
__global__ void __launch_bounds__(256) k_gemm(const float* __restrict__ W,
                                              const float* __restrict__ al,
                                              const float* __restrict__ ar) {
    __shared__ float xs[64][33];
    __shared__ float ws[32][132];
    __shared__ float us[128], vbs[128];
    __shared__ float A4[64][4];
    int tid = threadIdx.x;
    int tx = tid & 31, ty = tid >> 5;
    int row0 = blockIdx.x * 64;

    if (MODE == 0) {
        if (tid < 128) {
            us[tid] = g_u[tid];
            vbs[tid] = g_vb[tid];
        } else if (tid < 192) {
            int r = tid - 128;
            int grow = row0 + r;
            float4 a = (grow < NN) ? g_T[grow] : make_float4(0.f, 0.f, 0.f, 0.f);
            *(float4*)&A4[r][0] = a;
        }
        __syncthreads();
    }

    float acc[8][4];
#pragma unroll
    for (int r = 0; r < 8; r++)
#pragma unroll
        for (int c = 0; c < 4; c++) acc[r][c] = 0.f;

    for (int k0 = 0; k0 < 128; k0 += 32) {
        for (int i = tid; i < 64 * 32; i += 256) {
            int r = i >> 5, k = i & 31;
            int kk = k0 + k;
            float v;
            if (MODE == 0) {
                v = fmaf(A4[r][kk >> 5], us[kk], vbs[kk]);
            } else {
                int grow = row0 + r;
                v = (grow < NN) ? g_x0[grow * 128 + kk] : 0.f;
            }
            v = v >= 0.f ? v : 0.01f * v;  // layer>0 input activation
            xs[r][k] = v;
        }
        for (int i = tid; i < 128 * 32; i += 256) {
            int d = i >> 5, k = i & 31;
            ws[k][d] = W[d * 128 + k0 + k];
        }
        __syncthreads();
#pragma unroll
        for (int k = 0; k < 32; k++) {
            float4 b = *(const float4*)&ws[k][tx * 4];
#pragma unroll
            for (int r = 0; r < 8; r++) {
                float a = xs[ty * 8 + r][k];
                acc[r][0] = fmaf(a, b.x, acc[r][0]);
                acc[r][1] = fmaf(a, b.y, acc[r][1]);
                acc[r][2] = fmaf(a, b.z, acc[r][2]);
                acc[r][3] = fmaf(a, b.w, acc[r][3]);
            }
        }
        __syncthreads();
    }

    int col = tx * 4;
    float4 alv = *(const float4*)&al[col];
    float4 arv = *(const float4*)&ar[col];
#pragma unroll
    for (int r = 0; r < 8; r++) {
        int row = row0 + ty * 8 + r;
        if (row < NN) {
            *(float4*)&g_h[row * 128 + col] =
                make_float4(acc[r][0], acc[r][1], acc[r][2], acc[r][3]);
            float pl = acc[r][0] * alv.x + acc[r][1] * alv.y + acc[r][2] * alv.z + acc[r][3] * alv.w;
            float pr = acc[r][0] * arv.x + acc[r][1] * arv.y + acc[r][2] * arv.z + acc[r][3] * arv.w;
#pragma unroll
            for (int o = 4; o > 0; o >>= 1) {
                pl += __shfl_xor_sync(0xffffffffu, pl, o);
                pr += __shfl_xor_sync(0xffffffffu, pr, o);
            }
            if ((tx & 7) == 0) {
                int hh = tx >> 3;
                g_el[row * 4 + hh] = pl;
                g_er[row * 4 + hh] = pr;
            }
        }
    }
}

// ---------------- edge softmax + aggregation (layers 1,2) ------------------------
__device__ __forceinline__ float sel4(float4 v, int hh) {
    return (hh & 2) ? ((hh & 1) ? v.w : v.z) : ((hh & 1) ? v.y : v.x);
}

template <int FINAL>
__global__ void __launch_bounds__(256) k_agg(const float* __restrict__ bias,
                                             const float* __restrict__ pW,
                                             const float* __restrict__ pb,
                                             float* __restrict__ out) {
    int gw = (blockIdx.x * blockDim.x + threadIdx.x) >> 5;
    int lane = threadIdx.x & 31;
    if (gw >= NN) return;
    int n = gw;
    int beg = g_rowptr[n], end = g_rowptr[n + 1];
    float4 er4 = *(const float4*)&g_er[n * 4];

    float m0 = -3.4e38f, m1 = m0, m2 = m0, m3 = m0;
    for (int j = beg + lane; j < end; j += 32) {
        int s = g_csr[j];
        float4 el4 = *(const float4*)&g_el[s * 4];
        float e0 = el4.x + er4.x; e0 = e0 >= 0.f ? e0 : 0.2f * e0;
        float e1 = el4.y + er4.y; e1 = e1 >= 0.f ? e1 : 0.2f * e1;
        float e2 = el4.z + er4.z; e2 = e2 >= 0.f ? e2 : 0.2f * e2;
        float e3 = el4.w + er4.w; e3 = e3 >= 0.f ? e3 : 0.2f * e3;
        m0 = fmaxf(m0, e0); m1 = fmaxf(m1, e1);
        m2 = fmaxf(m2, e2); m3 = fmaxf(m3, e3);
    }
#pragma unroll
    for (int o = 16; o > 0; o >>= 1) {
        m0 = fmaxf(m0, __shfl_xor_sync(0xffffffffu, m0, o));
        m1 = fmaxf(m1, __shfl_xor_sync(0xffffffffu, m1, o));
        m2 = fmaxf(m2, __shfl_xor_sync(0xffffffffu, m2, o));
        m3 = fmaxf(m3, __shfl_xor_sync(0xffffffffu, m3, o));
    }

    int hh = lane >> 3;
    float mh = (hh & 2) ? ((hh & 1) ? m3 : m2) : ((hh & 1) ? m1 : m0);
    float erh = sel4(er4, hh);

    float a0 = 0.f, a1 = 0.f, a2 = 0.f, a3 = 0.f, sacc = 0.f;
    for (int j = beg; j < end; j++) {
        int s = g_csr[j];
        float4 el4 = *(const float4*)&g_el[s * 4];
        float e = sel4(el4, hh) + erh;
        e = e >= 0.f ? e : 0.2f * e;
        float p = __expf(e - mh);
        float4 hv = *(const float4*)&g_h[s * 128 + lane * 4];
        a0 = fmaf(p, hv.x, a0); a1 = fmaf(p, hv.y, a1);
        a2 = fmaf(p, hv.z, a2); a3 = fmaf(p, hv.w, a3);
        sacc += p;
    }
    float inv = 1.f / sacc;
    int col = lane * 4;
    float4 bv = *(const float4*)&bias[col];
    float4 o = make_float4(fmaf(a0, inv, bv.x), fmaf(a1, inv, bv.y),
                           fmaf(a2, inv, bv.z), fmaf(a3, inv, bv.w));
    if (FINAL) {
        float4 wv = *(const float4*)&pW[col];
        float s = o.x * wv.x + o.y * wv.y + o.z * wv.z + o.w * wv.w;
#pragma unroll
        for (int of = 16; of > 0; of >>= 1) s += __shfl_xor_sync(0xffffffffu, s, of);
        if (lane == 0) out[n] = s + pb[0];
    } else {
        *(float4*)&g_x0[n * 128 + col] = o;
    }
}

// ---------------- launch --------------------------------------------------------
extern "C" void kernel_launch(void* const* d_in, const int* in_sizes, int n_in,
                              void* d_out, int out_size) {
    const float* weights = (const float*)d_in[0];
    const float* linW    = (const float*)d_in[1];
    const float* linb    = (const float*)d_in[2];
    const float* fcW     = (const float*)d_in[3];
    const float* al      = (const float*)d_in[4];
    const float* ar      = (const float*)d_in[5];
    const float* cb      = (const float*)d_in[6];
    const float* pW      = (const float*)d_in[7];
    const float* pb      = (const float*)d_in[8];
    const int*   src     = (const int*)d_in[9];
    const int*   dst     = (const int*)d_in[10];
    float* out = (float*)d_out;

    k_cnt_init<<<(NN + 255) / 256, 256>>>();
    k_hist<<<(EE + 255) / 256, 256>>>(dst);
    k_scan<<<1, 1024>>>();
    k_scatter<<<(EE + NN + 255) / 256, 256>>>(src, dst);

    k_prep<<<1, 128>>>(fcW, linW, linb, al, ar, cb);

    const int GB = (NN + 63) / 64;
    const int AB = (NN * 32 + 255) / 256;

    // layer 0 (analytic): scalar edge softmax -> g_T
    k_agg0<<<AB, 256>>>(weights);
    // layer 1: x reconstructed from g_T
    k_gemm<0><<<GB, 256>>>(fcW + DD * DD, al + DD, ar + DD);
    k_agg<0><<<AB, 256>>>(cb + DD, pW, pb, out);
    // layer 2: x from g_x0; aggregation fused with prediction head
    k_gemm<1><<<GB, 256>>>(fcW + 2 * DD * DD, al + 2 * DD, ar + 2 * DD);
    k_agg<1><<<AB, 256>>>(cb + 2 * DD, pW, pb, out);
}